// round 10
// baseline (speedup 1.0000x reference)
#include <cuda_runtime.h>
#include <cuda_bf16.h>

// AnisotropicDistance:
// out[b,i,j] = alpha_i * max(||p_i-p_j||^2 + along^2*(||t_i||^2 - 2), 0) + beta_i * along^2
// along = (p_i.t_i) - (p_j.t_i)
//
// R9: fused single kernel, but j-side AoS->register conversion staged through
// shared memory (R8's stride-3 global loads tripled L1tex wavefronts and blew
// up alu%). Block's 1024 j-points (12 KB) loaded contiguously by all threads,
// then each thread LDSes its own 12 floats once. Hot loop identical to the
// 77.86us R7 config (TI=16, TPB=256, JV=4, f32x2, alpha-folded, __stcs).

typedef unsigned long long ull;

#define FMA2(d, a, b, c) asm("fma.rn.f32x2 %0, %1, %2, %3;" : "=l"(d) : "l"(a), "l"(b), "l"(c))
#define MUL2(d, a, b)    asm("mul.rn.f32x2 %0, %1, %2;"     : "=l"(d) : "l"(a), "l"(b))
#define PACK2(d, lo, hi) asm("mov.b64 %0, {%1, %2};"        : "=l"(d) : "f"(lo), "f"(hi))
#define UNPACK2(lo, hi, s) asm("mov.b64 {%0, %1}, %2;"      : "=f"(lo), "=f"(hi) : "l"(s))

__device__ __forceinline__ ull dup_f(float v) {
    ull d; PACK2(d, v, v); return d;
}

#define TI 16          // i-rows per block
#define TPB 256        // threads per block
#define JV 4           // j per thread (one float4 store) -> block covers 1024 j
#define JBLK (TPB * JV)            // 1024 j-points per block
#define PT_F4 (JBLK * 3 / 4)       // 768 float4s of point data per block

// Compute one packed pair (2 j-elements) -> result (max folded via alpha>0)
#define PAIR_COMPUTE(pjx, pjy, pjz, sqj, olo, ohi)                     \
    {                                                                  \
        ull u, a2, s, t2;                                              \
        FMA2(u, pjz, ntz, pds);                                        \
        FMA2(u, pjy, nty, u);                                          \
        FMA2(u, pjx, ntx, u);            /* along */                   \
        MUL2(a2, u, u);                  /* along^2 */                 \
        FMA2(s, pjz, alnpz, alsqi);                                    \
        FMA2(s, pjy, alnpy, s);                                        \
        FMA2(s, pjx, alnpx, s);          /* al*(sqi - 2 pj.pi) */      \
        FMA2(s, a2, alc1, s);            /* + al*c1*a2 */              \
        FMA2(s, al, sqj, s);             /* + al*sqj = al*ns */        \
        MUL2(t2, be, a2);                /* beta*a2 */                 \
        float s0, s1, b0, b1;                                          \
        UNPACK2(s0, s1, s);                                            \
        UNPACK2(b0, b1, t2);                                           \
        olo = fmaxf(s0, 0.0f) + b0;                                    \
        ohi = fmaxf(s1, 0.0f) + b1;                                    \
    }

__global__ __launch_bounds__(TPB, 4) void aniso_fused_kernel(
    const float* __restrict__ points,
    const float* __restrict__ pdir,
    const float* __restrict__ lin,
    float* __restrict__ out, int N) {
    __shared__ ulonglong2 s_c[TI * 6];
    __shared__ float4 s_pts[PT_F4];     // 12 KB staging of this block's j-points

    const int b  = blockIdx.z;
    const int i0 = blockIdx.y * TI;
    const int base = b * N;
    const int jblk0 = blockIdx.x * JBLK;          // first j of this block

    // ---- stage j-points: 12288 contiguous bytes, coalesced float4 loads ----
    // float index of block start: (base + jblk0)*3, divisible by 4.
    {
        const float4* p4 = reinterpret_cast<const float4*>(points) +
                           (((size_t)(base + jblk0) * 3) >> 2);
        #pragma unroll
        for (int k = 0; k < 3; k++)
            s_pts[threadIdx.x + k * TPB] = p4[threadIdx.x + k * TPB];
    }

    // ---- i-side constants: threads 0..15 compute from raw inputs ----
    if (threadIdx.x < TI) {
        const int gi = base + i0 + threadIdx.x;
        const float px = points[gi * 3 + 0];
        const float py = points[gi * 3 + 1];
        const float pz = points[gi * 3 + 2];
        const float tx = pdir[gi * 3 + 0];
        const float ty = pdir[gi * 3 + 1];
        const float tz = pdir[gi * 3 + 2];
        const float l  = lin[gi];

        const float sq = fmaf(px, px, fmaf(py, py, pz * pz));
        const float al = 2.0f * (1.0f + l);
        const float be = 0.5f * (1.0f - l);
        const float c1 = fmaf(tx, tx, fmaf(ty, ty, tz * tz)) - 2.0f;

        ulonglong2 c;
        c.x = dup_f(-tx);             c.y = dup_f(-ty);
        s_c[threadIdx.x * 6 + 0] = c;
        c.x = dup_f(-tz);             c.y = dup_f(fmaf(px, tx, fmaf(py, ty, pz * tz)));
        s_c[threadIdx.x * 6 + 1] = c;
        c.x = dup_f(al * -2.0f * px); c.y = dup_f(al * -2.0f * py);
        s_c[threadIdx.x * 6 + 2] = c;
        c.x = dup_f(al * -2.0f * pz); c.y = dup_f(al * c1);
        s_c[threadIdx.x * 6 + 3] = c;
        c.x = dup_f(al);              c.y = dup_f(be);
        s_c[threadIdx.x * 6 + 4] = c;
        c.x = dup_f(al * sq);         c.y = dup_f(al * sq);
        s_c[threadIdx.x * 6 + 5] = c;
    }
    __syncthreads();

    // ---- unstage this thread's 4 j-points (12 floats = 3 LDS.128) ----
    const float4 q0 = s_pts[threadIdx.x * 3 + 0];   // px0 py0 pz0 px1
    const float4 q1 = s_pts[threadIdx.x * 3 + 1];   // py1 pz1 px2 py2
    const float4 q2 = s_pts[threadIdx.x * 3 + 2];   // pz2 px3 py3 pz3

    ull ax01, ax23, ay01, ay23, az01, az23;
    PACK2(ax01, q0.x, q0.w); PACK2(ay01, q0.y, q1.x); PACK2(az01, q0.z, q1.y);
    PACK2(ax23, q1.z, q2.y); PACK2(ay23, q1.w, q2.z); PACK2(az23, q2.x, q2.w);

    // sqj computed in-registers (loop-invariant), packed f32x2
    ull as01, as23;
    {
        ull t;
        MUL2(t, az01, az01); FMA2(t, ay01, ay01, t); FMA2(as01, ax01, ax01, t);
        MUL2(t, az23, az23); FMA2(t, ay23, ay23, t); FMA2(as23, ax23, ax23, t);
    }

    float* orow = out + ((size_t)b * N + i0) * N + jblk0 + threadIdx.x * JV;

    #pragma unroll
    for (int ii = 0; ii < TI; ii++) {
        const ulonglong2 c0 = s_c[ii * 6 + 0];
        const ulonglong2 c1v = s_c[ii * 6 + 1];
        const ulonglong2 c2 = s_c[ii * 6 + 2];
        const ulonglong2 c3 = s_c[ii * 6 + 3];
        const ulonglong2 c4 = s_c[ii * 6 + 4];
        const ulonglong2 c5 = s_c[ii * 6 + 5];
        const ull ntx = c0.x, nty = c0.y, ntz = c1v.x, pds = c1v.y;
        const ull alnpx = c2.x, alnpy = c2.y, alnpz = c3.x, alc1 = c3.y;
        const ull al = c4.x, be = c4.y, alsqi = c5.x;

        float4 o;
        PAIR_COMPUTE(ax01, ay01, az01, as01, o.x, o.y);
        PAIR_COMPUTE(ax23, ay23, az23, as23, o.z, o.w);

        __stcs(reinterpret_cast<float4*>(orow), o);
        orow += N;
    }
}

extern "C" void kernel_launch(void* const* d_in, const int* in_sizes, int n_in,
                              void* d_out, int out_size) {
    const float* points = (const float*)d_in[0];
    const float* pdir   = (const float*)d_in[1];
    const float* lin    = (const float*)d_in[2];
    float* out = (float*)d_out;

    const int total = in_sizes[0] / 3;                 // B*N points
    const int N = (int)((long long)out_size / total);  // out = B*N*N
    const int B = total / N;

    dim3 grid((N + JBLK - 1) / JBLK, (N + TI - 1) / TI, B);
    aniso_fused_kernel<<<grid, TPB>>>(points, pdir, lin, out, N);
}

// round 12
// speedup vs baseline: 1.2157x; 1.2157x over previous
#include <cuda_runtime.h>
#include <cuda_bf16.h>

// AnisotropicDistance:
// out[b,i,j] = alpha_i * max(||p_i-p_j||^2 + along^2*(||t_i||^2 - 2), 0) + beta_i * along^2
// along = (p_i.t_i) - (p_j.t_i)
//
// R10: REVERT to the best-measured R7 two-kernel config (77.86us) — both fused
// variants regressed badly (88.8 / 94.7us, alu pipe blow-up). Single new lever:
// PDL (programmatic dependent launch) so the main kernel's launch overlaps the
// tiny precompute kernel; cudaGridDependencySynchronize() before reading the
// precomputed globals guarantees visibility. Kernel bodies unchanged.

#define MAX_PTS 32768  // B*N max supported (actual: 2*8192 = 16384)

typedef unsigned long long ull;

// j-side SoA:
__device__ float g_px[MAX_PTS];
__device__ float g_py[MAX_PTS];
__device__ float g_pz[MAX_PTS];
// i-side constants, duplicated (v,v) into b64, packed 2 consts per ulonglong2:
// slot 0: (ntx, nty)      slot 1: (ntz, pds)
// slot 2: (alnpx, alnpy)  slot 3: (alnpz, alc1)
// slot 4: (al, be)        slot 5: (alsqi, alsqi)
__device__ ulonglong2 g2c[MAX_PTS * 6];

#define FMA2(d, a, b, c) asm("fma.rn.f32x2 %0, %1, %2, %3;" : "=l"(d) : "l"(a), "l"(b), "l"(c))
#define MUL2(d, a, b)    asm("mul.rn.f32x2 %0, %1, %2;"     : "=l"(d) : "l"(a), "l"(b))
#define PACK2(d, lo, hi) asm("mov.b64 %0, {%1, %2};"        : "=l"(d) : "f"(lo), "f"(hi))
#define UNPACK2(lo, hi, s) asm("mov.b64 {%0, %1}, %2;"      : "=f"(lo), "=f"(hi) : "l"(s))

__device__ __forceinline__ ull dup_f(float v) {
    ull d; PACK2(d, v, v); return d;
}

__global__ void precompute_kernel(const float* __restrict__ points,
                                  const float* __restrict__ pdir,
                                  const float* __restrict__ lin,
                                  int total) {
    int idx = blockIdx.x * blockDim.x + threadIdx.x;
    if (idx >= total) return;
    float px = points[idx * 3 + 0];
    float py = points[idx * 3 + 1];
    float pz = points[idx * 3 + 2];
    float tx = pdir[idx * 3 + 0];
    float ty = pdir[idx * 3 + 1];
    float tz = pdir[idx * 3 + 2];
    float l  = lin[idx];

    g_px[idx] = px; g_py[idx] = py; g_pz[idx] = pz;
    float sq = fmaf(px, px, fmaf(py, py, pz * pz));

    float al = 2.0f * (1.0f + l);
    float be = 0.5f * (1.0f - l);
    float c1 = fmaf(tx, tx, fmaf(ty, ty, tz * tz)) - 2.0f;

    ulonglong2 c;
    c.x = dup_f(-tx);             c.y = dup_f(-ty);
    g2c[idx * 6 + 0] = c;
    c.x = dup_f(-tz);             c.y = dup_f(fmaf(px, tx, fmaf(py, ty, pz * tz)));
    g2c[idx * 6 + 1] = c;
    c.x = dup_f(al * -2.0f * px); c.y = dup_f(al * -2.0f * py);
    g2c[idx * 6 + 2] = c;
    c.x = dup_f(al * -2.0f * pz); c.y = dup_f(al * c1);
    g2c[idx * 6 + 3] = c;
    c.x = dup_f(al);              c.y = dup_f(be);
    g2c[idx * 6 + 4] = c;
    c.x = dup_f(al * sq);         c.y = dup_f(al * sq);
    g2c[idx * 6 + 5] = c;
}

#define TI 16          // i-rows per block
#define TPB 256        // threads per block
#define JV 4           // j per thread (one float4 store) -> block covers 1024 j

// Compute one packed pair (2 j-elements) -> result (max folded via alpha>0)
#define PAIR_COMPUTE(pjx, pjy, pjz, sqj, olo, ohi)                     \
    {                                                                  \
        ull u, a2, s, t2;                                              \
        FMA2(u, pjz, ntz, pds);                                        \
        FMA2(u, pjy, nty, u);                                          \
        FMA2(u, pjx, ntx, u);            /* along */                   \
        MUL2(a2, u, u);                  /* along^2 */                 \
        FMA2(s, pjz, alnpz, alsqi);                                    \
        FMA2(s, pjy, alnpy, s);                                        \
        FMA2(s, pjx, alnpx, s);          /* al*(sqi - 2 pj.pi) */      \
        FMA2(s, a2, alc1, s);            /* + al*c1*a2 */              \
        FMA2(s, al, sqj, s);             /* + al*sqj = al*ns */        \
        MUL2(t2, be, a2);                /* beta*a2 */                 \
        float s0, s1, b0, b1;                                          \
        UNPACK2(s0, s1, s);                                            \
        UNPACK2(b0, b1, t2);                                           \
        olo = fmaxf(s0, 0.0f) + b0;                                    \
        ohi = fmaxf(s1, 0.0f) + b1;                                    \
    }

__global__ __launch_bounds__(TPB, 4) void aniso_main_kernel(float* __restrict__ out, int N) {
    __shared__ ulonglong2 s_c[TI * 6];

    // PDL: wait until precompute_kernel's global writes are visible.
    cudaGridDependencySynchronize();

    const int b  = blockIdx.z;
    const int i0 = blockIdx.y * TI;
    const int j4 = blockIdx.x * TPB + threadIdx.x;   // float4 index in j
    const int j  = j4 * JV;
    const int base = b * N;

    if (threadIdx.x < TI * 6) {
        s_c[threadIdx.x] = g2c[(base + i0) * 6 + threadIdx.x];
    }
    __syncthreads();

    if (j >= N) return;

    // j-side loads (coalesced float4, L2-resident), packed into b64 pairs once
    const float4 pjx = reinterpret_cast<const float4*>(g_px + base)[j4];
    const float4 pjy = reinterpret_cast<const float4*>(g_py + base)[j4];
    const float4 pjz = reinterpret_cast<const float4*>(g_pz + base)[j4];

    ull ax01, ax23, ay01, ay23, az01, az23;
    PACK2(ax01, pjx.x, pjx.y); PACK2(ax23, pjx.z, pjx.w);
    PACK2(ay01, pjy.x, pjy.y); PACK2(ay23, pjy.z, pjy.w);
    PACK2(az01, pjz.x, pjz.y); PACK2(az23, pjz.z, pjz.w);

    // sqj computed in-registers (loop-invariant), packed f32x2
    ull as01, as23;
    {
        ull t;
        MUL2(t, az01, az01); FMA2(t, ay01, ay01, t); FMA2(as01, ax01, ax01, t);
        MUL2(t, az23, az23); FMA2(t, ay23, ay23, t); FMA2(as23, ax23, ax23, t);
    }

    float* orow = out + ((size_t)b * N + i0) * N + j;

    #pragma unroll
    for (int ii = 0; ii < TI; ii++) {
        const ulonglong2 c0 = s_c[ii * 6 + 0];
        const ulonglong2 c1v = s_c[ii * 6 + 1];
        const ulonglong2 c2 = s_c[ii * 6 + 2];
        const ulonglong2 c3 = s_c[ii * 6 + 3];
        const ulonglong2 c4 = s_c[ii * 6 + 4];
        const ulonglong2 c5 = s_c[ii * 6 + 5];
        const ull ntx = c0.x, nty = c0.y, ntz = c1v.x, pds = c1v.y;
        const ull alnpx = c2.x, alnpy = c2.y, alnpz = c3.x, alc1 = c3.y;
        const ull al = c4.x, be = c4.y, alsqi = c5.x;

        float4 o;
        PAIR_COMPUTE(ax01, ay01, az01, as01, o.x, o.y);
        PAIR_COMPUTE(ax23, ay23, az23, as23, o.z, o.w);

        __stcs(reinterpret_cast<float4*>(orow), o);
        orow += N;
    }
}

extern "C" void kernel_launch(void* const* d_in, const int* in_sizes, int n_in,
                              void* d_out, int out_size) {
    const float* points = (const float*)d_in[0];
    const float* pdir   = (const float*)d_in[1];
    const float* lin    = (const float*)d_in[2];
    float* out = (float*)d_out;

    const int total = in_sizes[0] / 3;                 // B*N points
    const int N = (int)((long long)out_size / total);  // out = B*N*N
    const int B = total / N;

    precompute_kernel<<<(total + 255) / 256, 256>>>(points, pdir, lin, total);

    // Main kernel with PDL: launch overlaps precompute execution; the in-kernel
    // cudaGridDependencySynchronize() enforces the data dependency.
    dim3 grid((N + TPB * JV - 1) / (TPB * JV), (N + TI - 1) / TI, B);

    cudaLaunchConfig_t cfg = {};
    cfg.gridDim = grid;
    cfg.blockDim = dim3(TPB, 1, 1);
    cfg.dynamicSmemBytes = 0;
    cfg.stream = 0;
    cudaLaunchAttribute attrs[1];
    attrs[0].id = cudaLaunchAttributeProgrammaticStreamSerialization;
    attrs[0].val.programmaticStreamSerializationAllowed = 1;
    cfg.attrs = attrs;
    cfg.numAttrs = 1;
    cudaLaunchKernelEx(&cfg, aniso_main_kernel, out, N);
}

// round 13
// speedup vs baseline: 1.2162x; 1.0004x over previous
#include <cuda_runtime.h>
#include <cuda_bf16.h>

// AnisotropicDistance:
// out[b,i,j] = alpha_i * max(||p_i-p_j||^2 + along^2*(||t_i||^2 - 2), 0) + beta_i * along^2
// along = (p_i.t_i) - (p_j.t_i)
//
// R12: drop the max() clamp (normal_sq >= 0 mathematically for any t, by
// Cauchy-Schwarz; clamp only guards ~1e-7 fp rounding, gate is 1e-3) and fold
// beta into the chain: out = al*sq_dist + g*a2 with g = al*c1 + be. Epilogue
// vanishes: 9 FMA2 per packed pair, result stored packed (no unpack/fmax/add),
// 10 constants -> 5 LDS.128 per iteration. PDL kept from R10.

#define MAX_PTS 32768  // B*N max supported (actual: 2*8192 = 16384)

typedef unsigned long long ull;

// j-side SoA:
__device__ float g_px[MAX_PTS];
__device__ float g_py[MAX_PTS];
__device__ float g_pz[MAX_PTS];
// i-side constants, duplicated (v,v) into b64, packed 2 per ulonglong2:
// slot 0: (ntx, nty)      slot 1: (ntz, pds)
// slot 2: (alnpx, alnpy)  slot 3: (alnpz, g)     g = al*c1 + be
// slot 4: (al, alsqi)
__device__ ulonglong2 g2c[MAX_PTS * 5];

#define FMA2(d, a, b, c) asm("fma.rn.f32x2 %0, %1, %2, %3;" : "=l"(d) : "l"(a), "l"(b), "l"(c))
#define MUL2(d, a, b)    asm("mul.rn.f32x2 %0, %1, %2;"     : "=l"(d) : "l"(a), "l"(b))
#define PACK2(d, lo, hi) asm("mov.b64 %0, {%1, %2};"        : "=l"(d) : "f"(lo), "f"(hi))

__device__ __forceinline__ ull dup_f(float v) {
    ull d; PACK2(d, v, v); return d;
}

__global__ void precompute_kernel(const float* __restrict__ points,
                                  const float* __restrict__ pdir,
                                  const float* __restrict__ lin,
                                  int total) {
    int idx = blockIdx.x * blockDim.x + threadIdx.x;
    if (idx >= total) return;
    float px = points[idx * 3 + 0];
    float py = points[idx * 3 + 1];
    float pz = points[idx * 3 + 2];
    float tx = pdir[idx * 3 + 0];
    float ty = pdir[idx * 3 + 1];
    float tz = pdir[idx * 3 + 2];
    float l  = lin[idx];

    g_px[idx] = px; g_py[idx] = py; g_pz[idx] = pz;
    float sq = fmaf(px, px, fmaf(py, py, pz * pz));

    float al = 2.0f * (1.0f + l);
    float be = 0.5f * (1.0f - l);
    float c1 = fmaf(tx, tx, fmaf(ty, ty, tz * tz)) - 2.0f;
    float g  = fmaf(al, c1, be);          // al*c1 + be

    ulonglong2 c;
    c.x = dup_f(-tx);             c.y = dup_f(-ty);
    g2c[idx * 5 + 0] = c;
    c.x = dup_f(-tz);             c.y = dup_f(fmaf(px, tx, fmaf(py, ty, pz * tz)));
    g2c[idx * 5 + 1] = c;
    c.x = dup_f(al * -2.0f * px); c.y = dup_f(al * -2.0f * py);
    g2c[idx * 5 + 2] = c;
    c.x = dup_f(al * -2.0f * pz); c.y = dup_f(g);
    g2c[idx * 5 + 3] = c;
    c.x = dup_f(al);              c.y = dup_f(al * sq);
    g2c[idx * 5 + 4] = c;
}

#define TI 16          // i-rows per block
#define TPB 256        // threads per block
#define JV 4           // j per thread (one 16B store) -> block covers 1024 j

// One packed pair (2 j-elements) -> packed result in 'res' (no epilogue):
// res = al*(sqi - 2 pj.pi + sqj) + g*along^2
#define PAIR_COMPUTE(pjx, pjy, pjz, sqj, res)                          \
    {                                                                  \
        ull u, a2;                                                     \
        FMA2(u, pjz, ntz, pds);                                        \
        FMA2(u, pjy, nty, u);                                          \
        FMA2(u, pjx, ntx, u);            /* along */                   \
        MUL2(a2, u, u);                  /* along^2 */                 \
        FMA2(res, pjz, alnpz, alsqi);                                  \
        FMA2(res, pjy, alnpy, res);                                    \
        FMA2(res, pjx, alnpx, res);      /* al*(sqi - 2 pj.pi) */      \
        FMA2(res, al, sqj, res);         /* + al*sqj */                \
        FMA2(res, a2, gg, res);          /* + (al*c1+be)*a2 */         \
    }

__global__ __launch_bounds__(TPB, 4) void aniso_main_kernel(float* __restrict__ out, int N) {
    __shared__ ulonglong2 s_c[TI * 5];

    // PDL: wait until precompute_kernel's global writes are visible.
    cudaGridDependencySynchronize();

    const int b  = blockIdx.z;
    const int i0 = blockIdx.y * TI;
    const int j4 = blockIdx.x * TPB + threadIdx.x;   // float4 index in j
    const int j  = j4 * JV;
    const int base = b * N;

    if (threadIdx.x < TI * 5) {
        s_c[threadIdx.x] = g2c[(base + i0) * 5 + threadIdx.x];
    }
    __syncthreads();

    if (j >= N) return;

    // j-side loads (coalesced float4, L2-resident), packed into b64 pairs once
    const float4 pjx = reinterpret_cast<const float4*>(g_px + base)[j4];
    const float4 pjy = reinterpret_cast<const float4*>(g_py + base)[j4];
    const float4 pjz = reinterpret_cast<const float4*>(g_pz + base)[j4];

    ull ax01, ax23, ay01, ay23, az01, az23;
    PACK2(ax01, pjx.x, pjx.y); PACK2(ax23, pjx.z, pjx.w);
    PACK2(ay01, pjy.x, pjy.y); PACK2(ay23, pjy.z, pjy.w);
    PACK2(az01, pjz.x, pjz.y); PACK2(az23, pjz.z, pjz.w);

    // sqj computed in-registers (loop-invariant), packed f32x2
    ull as01, as23;
    {
        ull t;
        MUL2(t, az01, az01); FMA2(t, ay01, ay01, t); FMA2(as01, ax01, ax01, t);
        MUL2(t, az23, az23); FMA2(t, ay23, ay23, t); FMA2(as23, ax23, ax23, t);
    }

    float* orow = out + ((size_t)b * N + i0) * N + j;

    #pragma unroll
    for (int ii = 0; ii < TI; ii++) {
        const ulonglong2 c0 = s_c[ii * 5 + 0];
        const ulonglong2 c1v = s_c[ii * 5 + 1];
        const ulonglong2 c2 = s_c[ii * 5 + 2];
        const ulonglong2 c3 = s_c[ii * 5 + 3];
        const ulonglong2 c4 = s_c[ii * 5 + 4];
        const ull ntx = c0.x, nty = c0.y, ntz = c1v.x, pds = c1v.y;
        const ull alnpx = c2.x, alnpy = c2.y, alnpz = c3.x, gg = c3.y;
        const ull al = c4.x, alsqi = c4.y;

        ulonglong2 o;
        PAIR_COMPUTE(ax01, ay01, az01, as01, o.x);
        PAIR_COMPUTE(ax23, ay23, az23, as23, o.y);

        __stcs(reinterpret_cast<ulonglong2*>(orow), o);   // 16B streaming store
        orow += N;
    }
}

extern "C" void kernel_launch(void* const* d_in, const int* in_sizes, int n_in,
                              void* d_out, int out_size) {
    const float* points = (const float*)d_in[0];
    const float* pdir   = (const float*)d_in[1];
    const float* lin    = (const float*)d_in[2];
    float* out = (float*)d_out;

    const int total = in_sizes[0] / 3;                 // B*N points
    const int N = (int)((long long)out_size / total);  // out = B*N*N
    const int B = total / N;

    precompute_kernel<<<(total + 255) / 256, 256>>>(points, pdir, lin, total);

    // Main kernel with PDL: launch overlaps precompute execution.
    dim3 grid((N + TPB * JV - 1) / (TPB * JV), (N + TI - 1) / TI, B);

    cudaLaunchConfig_t cfg = {};
    cfg.gridDim = grid;
    cfg.blockDim = dim3(TPB, 1, 1);
    cfg.dynamicSmemBytes = 0;
    cfg.stream = 0;
    cudaLaunchAttribute attrs[1];
    attrs[0].id = cudaLaunchAttributeProgrammaticStreamSerialization;
    attrs[0].val.programmaticStreamSerializationAllowed = 1;
    cfg.attrs = attrs;
    cfg.numAttrs = 1;
    cudaLaunchKernelEx(&cfg, aniso_main_kernel, out, N);
}